// round 1
// baseline (speedup 1.0000x reference)
#include <cuda_runtime.h>
#include <math.h>

#define AN 4096
#define CN 8
#define FN 64
#define TM 64
#define TN 128
#define NTHREADS 256

// scratch (device globals — no allocation allowed)
__device__ float g_xn[CN * AN * FN];     // [c][a][f] normalized, channel-major
__device__ int   g_idx[CN * AN];         // [c][a] argmax index
__device__ float g_partial[256];         // per-block loss partials

// ---------------------------------------------------------------------------
// Kernel 1: row-normalize + relayout (a,c,f) -> (c,a,f)
// one warp per (a,c) row; lane holds float2 (64 floats / 32 lanes)
// ---------------------------------------------------------------------------
__global__ void k_normalize(const float* __restrict__ x) {
    int warp = (blockIdx.x * blockDim.x + threadIdx.x) >> 5;
    int lane = threadIdx.x & 31;
    if (warp >= AN * CN) return;
    int a = warp / CN;
    int c = warp % CN;
    const float2* row = (const float2*)(x + ((size_t)a * CN + c) * FN);
    float2 v = row[lane];
    float ss = v.x * v.x + v.y * v.y;
    #pragma unroll
    for (int o = 16; o > 0; o >>= 1) ss += __shfl_xor_sync(0xffffffffu, ss, o);
    float inv = 1.0f / fmaxf(sqrtf(ss), 1e-6f);
    float2* dst = (float2*)(g_xn + ((size_t)c * AN + a) * FN);
    dst[lane] = make_float2(v.x * inv, v.y * inv);
}

// ---------------------------------------------------------------------------
// Kernel 2: per-channel sim GEMM with streaming row-argmax epilogue.
// Block: TM=64 rows x (all 4096 cols in TN=128 tiles), 256 threads.
// Thread tile 4 rows x 8 cols. Smem tiles stored transposed [k][i] so the
// k-loop reads are broadcast/conflict-light.
// ---------------------------------------------------------------------------
__global__ void k_argmax() {
    __shared__ float As[FN * TM];   // [k][r]  64*64  = 16 KB
    __shared__ float Bs[FN * TN];   // [k][r]  64*128 = 32 KB

    int c = blockIdx.y;
    int row0 = blockIdx.x * TM;
    const float* xc = g_xn + (size_t)c * AN * FN;

    // load A tile (transposed store)
    for (int s = threadIdx.x; s < TM * (FN / 4); s += NTHREADS) {
        int r  = s >> 4;
        int k4 = s & 15;
        float4 v = ((const float4*)(xc + (size_t)(row0 + r) * FN))[k4];
        int kk = k4 * 4;
        As[(kk + 0) * TM + r] = v.x;
        As[(kk + 1) * TM + r] = v.y;
        As[(kk + 2) * TM + r] = v.z;
        As[(kk + 3) * TM + r] = v.w;
    }

    int tx = threadIdx.x & 15;   // col group: 16 groups x 8 cols = 128
    int ty = threadIdx.x >> 4;   // row group: 16 groups x 4 rows = 64

    float best[4];
    int   bidx[4];
    #pragma unroll
    for (int i = 0; i < 4; i++) { best[i] = -2.0f; bidx[i] = 0; }

    for (int col0 = 0; col0 < AN; col0 += TN) {
        __syncthreads();
        // load B tile (transposed store)
        for (int s = threadIdx.x; s < TN * (FN / 4); s += NTHREADS) {
            int r  = s >> 4;
            int k4 = s & 15;
            float4 v = ((const float4*)(xc + (size_t)(col0 + r) * FN))[k4];
            int kk = k4 * 4;
            Bs[(kk + 0) * TN + r] = v.x;
            Bs[(kk + 1) * TN + r] = v.y;
            Bs[(kk + 2) * TN + r] = v.z;
            Bs[(kk + 3) * TN + r] = v.w;
        }
        __syncthreads();

        float acc[4][8];
        #pragma unroll
        for (int i = 0; i < 4; i++)
            #pragma unroll
            for (int j = 0; j < 8; j++) acc[i][j] = 0.0f;

        #pragma unroll 8
        for (int k = 0; k < FN; k++) {
            float4 av = *(const float4*)(As + k * TM + ty * 4);
            float4 b0 = *(const float4*)(Bs + k * TN + tx * 8);
            float4 b1 = *(const float4*)(Bs + k * TN + tx * 8 + 4);
            float ar[4] = {av.x, av.y, av.z, av.w};
            float br[8] = {b0.x, b0.y, b0.z, b0.w, b1.x, b1.y, b1.z, b1.w};
            #pragma unroll
            for (int i = 0; i < 4; i++)
                #pragma unroll
                for (int j = 0; j < 8; j++)
                    acc[i][j] = fmaf(ar[i], br[j], acc[i][j]);
        }

        // streaming argmax update (ascending gb per thread -> strict > gives
        // first-index tie-break semantics, matching jnp.argmax)
        #pragma unroll
        for (int i = 0; i < 4; i++) {
            int ga = row0 + ty * 4 + i;
            #pragma unroll
            for (int j = 0; j < 8; j++) {
                int gb = col0 + tx * 8 + j;
                float v = (gb == ga) ? -2.0f : acc[i][j];  // exclude diagonal
                if (v > best[i]) { best[i] = v; bidx[i] = gb; }
            }
        }
    }

    // reduce over the 16 tx-threads sharing the same rows (width-16 shfl,
    // consecutive lanes -> segments align). Lexicographic max by (v, -idx).
    #pragma unroll
    for (int i = 0; i < 4; i++) {
        float v = best[i];
        int   bi = bidx[i];
        #pragma unroll
        for (int o = 8; o > 0; o >>= 1) {
            float ov = __shfl_down_sync(0xffffffffu, v, o, 16);
            int   oi = __shfl_down_sync(0xffffffffu, bi, o, 16);
            if (ov > v || (ov == v && oi < bi)) { v = ov; bi = oi; }
        }
        if (tx == 0) g_idx[(size_t)c * AN + row0 + ty * 4 + i] = bi;
    }
}

// ---------------------------------------------------------------------------
// Kernel 3: per-pair distance + partial loss sum. One warp per (c,a) item.
// PDIST_EPS is added componentwise BEFORE the norm (so recompute, don't use
// 2-2*sim). Deterministic: fixed warp/block reduction order.
// ---------------------------------------------------------------------------
__global__ void k_dist() {
    int gwarp  = (blockIdx.x * blockDim.x + threadIdx.x) >> 5;
    int lane   = threadIdx.x & 31;
    int nwarps = (gridDim.x * blockDim.x) >> 5;
    float acc = 0.0f;
    for (int item = gwarp; item < CN * AN; item += nwarps) {
        int b = g_idx[item];
        int c = item >> 12;      // item = c*4096 + a
        const float2* pa = (const float2*)(g_xn + ((size_t)item) * FN);
        const float2* pb = (const float2*)(g_xn + ((size_t)c * AN + b) * FN);
        float2 va = pa[lane];
        float2 vb = pb[lane];
        float dx = va.x - vb.x + 1e-6f;
        float dy = va.y - vb.y + 1e-6f;
        float ss = dx * dx + dy * dy;
        #pragma unroll
        for (int o = 16; o > 0; o >>= 1) ss += __shfl_xor_sync(0xffffffffu, ss, o);
        if (lane == 0) acc -= logf(sqrtf(ss) + 1e-6f);
    }
    __shared__ float wsum[8];
    if (lane == 0) wsum[threadIdx.x >> 5] = acc;
    __syncthreads();
    if (threadIdx.x == 0) {
        float s = 0.0f;
        #pragma unroll
        for (int i = 0; i < 8; i++) s += wsum[i];
        g_partial[blockIdx.x] = s;
    }
}

// ---------------------------------------------------------------------------
// Kernel 4: final reduction -> loss scalar
// ---------------------------------------------------------------------------
__global__ void k_final(float* __restrict__ out) {
    __shared__ float sm[256];
    sm[threadIdx.x] = g_partial[threadIdx.x];
    __syncthreads();
    for (int s = 128; s > 0; s >>= 1) {
        if (threadIdx.x < s) sm[threadIdx.x] += sm[threadIdx.x + s];
        __syncthreads();
    }
    if (threadIdx.x == 0) out[0] = sm[0] / (float)(CN * AN);
}

extern "C" void kernel_launch(void* const* d_in, const int* in_sizes, int n_in,
                              void* d_out, int out_size) {
    const float* x = (const float*)d_in[0];
    float* out = (float*)d_out;
    (void)in_sizes; (void)n_in; (void)out_size;

    k_normalize<<<(AN * CN) / 8, NTHREADS>>>(x);          // 8 warps/block
    k_argmax<<<dim3(AN / TM, CN), NTHREADS>>>();          // 64x8 = 512 blocks
    k_dist<<<256, NTHREADS>>>();
    k_final<<<1, 256>>>(out);
}

// round 3
// speedup vs baseline: 4.3289x; 4.3289x over previous
#include <cuda_runtime.h>
#include <cuda_bf16.h>
#include <math.h>
#include <stdint.h>

#define AN 4096
#define CN 8
#define FN 64
#define NTHREADS 256

// ---------------- device scratch (no allocation allowed) --------------------
__device__ float          g_xn[CN * AN * FN];    // [c][a][f] normalized fp32
__device__ __nv_bfloat16  g_xp[CN * AN * 128];   // [c][a][hi(64) | lo(64)] bf16
__device__ int            g_idx[CN * AN];
__device__ float          g_partial[256];

// ---------------- PTX helpers (generic sm_80+ ISA only!) --------------------
static __device__ __forceinline__ uint32_t smem_u32(const void* p) {
    uint32_t a;
    asm("{ .reg .u64 t; cvta.to.shared.u64 t, %1; cvt.u32.u64 %0, t; }"
        : "=r"(a) : "l"(p));
    return a;
}

#define CP16(dst, src) \
    asm volatile("cp.async.cg.shared.global [%0], [%1], 16;" :: "r"(dst), "l"(src))
#define CP_COMMIT() asm volatile("cp.async.commit_group;" ::: "memory")
#define CP_WAIT0()  asm volatile("cp.async.wait_group 0;" ::: "memory")

static __device__ __forceinline__ void ldsm_x4(uint32_t* d, uint32_t addr) {
    asm volatile("ldmatrix.sync.aligned.m8n8.x4.shared.b16 {%0,%1,%2,%3}, [%4];"
                 : "=r"(d[0]), "=r"(d[1]), "=r"(d[2]), "=r"(d[3]) : "r"(addr));
}

static __device__ __forceinline__ void mma_bf16(float* c, const uint32_t* a,
                                                const uint32_t* b) {
    asm volatile(
        "mma.sync.aligned.m16n8k16.row.col.f32.bf16.bf16.f32 "
        "{%0,%1,%2,%3}, {%4,%5,%6,%7}, {%8,%9}, {%0,%1,%2,%3};"
        : "+f"(c[0]), "+f"(c[1]), "+f"(c[2]), "+f"(c[3])
        : "r"(a[0]), "r"(a[1]), "r"(a[2]), "r"(a[3]), "r"(b[0]), "r"(b[1]));
}

// swizzled byte offset of 16B chunk (r, ch) in a 128-row x 256B tile.
// XOR of chunk low-3 bits with row low-3 bits -> conflict-free ldmatrix.
static __device__ __forceinline__ uint32_t swz(uint32_t r, uint32_t ch) {
    return r * 256u + (((ch & 8u) | ((ch ^ r) & 7u)) << 4);
}

// ---------------------------------------------------------------------------
// Kernel 1: normalize rows, write fp32 (c-major) + bf16 hi/lo split
// ---------------------------------------------------------------------------
__global__ void k_normalize(const float* __restrict__ x) {
    int warp = (blockIdx.x * blockDim.x + threadIdx.x) >> 5;
    int lane = threadIdx.x & 31;
    if (warp >= AN * CN) return;
    int a = warp / CN;
    int c = warp % CN;
    const float2* row = (const float2*)(x + ((size_t)a * CN + c) * FN);
    float2 v = row[lane];
    float ss = v.x * v.x + v.y * v.y;
    #pragma unroll
    for (int o = 16; o > 0; o >>= 1) ss += __shfl_xor_sync(0xffffffffu, ss, o);
    float inv = 1.0f / fmaxf(sqrtf(ss), 1e-6f);
    float nx = v.x * inv, ny = v.y * inv;

    float2* dst = (float2*)(g_xn + ((size_t)c * AN + a) * FN);
    dst[lane] = make_float2(nx, ny);

    __nv_bfloat16 hx = __float2bfloat16(nx);
    __nv_bfloat16 hy = __float2bfloat16(ny);
    __nv_bfloat16 lx = __float2bfloat16(nx - __bfloat162float(hx));
    __nv_bfloat16 ly = __float2bfloat16(ny - __bfloat162float(hy));
    __nv_bfloat16* base = g_xp + ((size_t)c * AN + a) * 128;
    __nv_bfloat162 h2; h2.x = hx; h2.y = hy;
    __nv_bfloat162 l2; l2.x = lx; l2.y = ly;
    ((__nv_bfloat162*)base)[lane]        = h2;   // hi at [0,64)
    ((__nv_bfloat162*)(base + 64))[lane] = l2;   // lo at [64,128)
}

// ---------------------------------------------------------------------------
// Kernel 2: mma.sync bf16 3-term GEMM + streaming row-argmax.
// CTA: 128 rows of one channel, loop 32 col-tiles of 128.
// 8 warps = 2 (m) x 4 (n); warp tile 64x32; acc in registers.
// smem: A 32KB | B0 32KB | B1 32KB | redv 2KB | redi 2KB
// ---------------------------------------------------------------------------
#define SM_A   0
#define SM_B0  32768
#define SM_B1  65536
#define SM_RV  98304
#define SM_RI  100352
#define SMEM_BYTES 102400

extern __shared__ __align__(1024) uint8_t dsm[];

__global__ __launch_bounds__(NTHREADS, 2) void k_argmax_mma() {
    uint32_t sb = smem_u32(dsm);
    int tid = threadIdx.x;
    int lane = tid & 31;
    int wid = tid >> 5;
    int wm = wid >> 2;         // 0..1
    int wn = wid & 3;          // 0..3
    int c = blockIdx.y;
    int row0 = blockIdx.x * 128;

    const char* xc = (const char*)(g_xp + (size_t)c * AN * 128);  // 256B rows

    // ---- prologue: A tile + B tile 0 via cp.async ----
    #pragma unroll
    for (int i = 0; i < 8; i++) {
        int s = tid + i * NTHREADS;        // 0..2047
        uint32_t r = (uint32_t)(s >> 4), ch = (uint32_t)(s & 15);
        CP16(sb + SM_A  + swz(r, ch), xc + (size_t)(row0 + r) * 256 + ch * 16);
        CP16(sb + SM_B0 + swz(r, ch), xc + (size_t)r * 256 + ch * 16);
    }
    CP_COMMIT();
    CP_WAIT0();
    __syncthreads();

    // per-thread running argmax: 8 row-slots (4 mi x 2 halves)
    float best[8];
    int   bidx[8];
    #pragma unroll
    for (int s = 0; s < 8; s++) { best[s] = -2.0f; bidx[s] = 0; }

    // ldmatrix lane-address components (constant per thread)
    uint32_t a_rl = (uint32_t)((lane & 7) + ((lane >> 3) & 1) * 8);  // A row-local
    uint32_t a_cs = (uint32_t)(lane >> 4);                           // A chunk sub
    uint32_t b_nl = (uint32_t)((lane & 7) + (lane >> 4) * 8);        // B n-local
    uint32_t b_cs = (uint32_t)((lane >> 3) & 1);                     // B chunk sub

    for (int t = 0; t < 32; t++) {
        uint32_t bufc = sb + ((t & 1) ? SM_B1 : SM_B0);
        // prefetch next B tile into the other buffer
        if (t + 1 < 32) {
            uint32_t bufn = sb + ((t & 1) ? SM_B0 : SM_B1);
            const char* bsrc = xc + (size_t)(t + 1) * 128 * 256;
            #pragma unroll
            for (int i = 0; i < 8; i++) {
                int s = tid + i * NTHREADS;
                uint32_t r = (uint32_t)(s >> 4), ch = (uint32_t)(s & 15);
                CP16(bufn + swz(r, ch), bsrc + (size_t)r * 256 + ch * 16);
            }
            CP_COMMIT();
        }

        float acc[4][4][4];
        #pragma unroll
        for (int mi = 0; mi < 4; mi++)
            #pragma unroll
            for (int ni = 0; ni < 4; ni++)
                #pragma unroll
                for (int q = 0; q < 4; q++) acc[mi][ni][q] = 0.0f;

        #pragma unroll
        for (int term = 0; term < 3; term++) {
            const uint32_t ha = (term == 2) ? 8u : 0u;   // A chunk base (hi/lo)
            const uint32_t hb = (term == 1) ? 8u : 0u;   // B chunk base
            #pragma unroll
            for (int ks = 0; ks < 4; ks++) {
                uint32_t acb = ha + (uint32_t)(ks * 2);
                uint32_t bcb = hb + (uint32_t)(ks * 2);
                uint32_t af[4][4], bf[2][4];
                #pragma unroll
                for (int mi = 0; mi < 4; mi++) {
                    uint32_t r = (uint32_t)(wm * 64 + mi * 16) + a_rl;
                    ldsm_x4(af[mi], sb + SM_A + swz(r, acb + a_cs));
                }
                #pragma unroll
                for (int nh = 0; nh < 2; nh++) {
                    uint32_t n = (uint32_t)(wn * 32 + nh * 16) + b_nl;
                    ldsm_x4(bf[nh], bufc + swz(n, bcb + b_cs));
                }
                #pragma unroll
                for (int mi = 0; mi < 4; mi++)
                    #pragma unroll
                    for (int ni = 0; ni < 4; ni++)
                        mma_bf16(acc[mi][ni], af[mi], &bf[ni >> 1][(ni & 1) * 2]);
            }
        }

        // streaming argmax update
        bool dt = (t == (int)blockIdx.x);
        #pragma unroll
        for (int mi = 0; mi < 4; mi++) {
            #pragma unroll
            for (int h = 0; h < 2; h++) {
                int slot = mi * 2 + h;
                int lrow = wm * 64 + mi * 16 + (lane >> 2) + h * 8;
                #pragma unroll
                for (int ni = 0; ni < 4; ni++) {
                    #pragma unroll
                    for (int q = 0; q < 2; q++) {
                        float v = acc[mi][ni][h * 2 + q];
                        int cc = wn * 32 + ni * 8 + (lane & 3) * 2 + q;
                        if (dt && cc == lrow) v = -2.0f;   // diagonal
                        if (v > best[slot]) { best[slot] = v; bidx[slot] = t * 128 + cc; }
                    }
                }
            }
        }

        CP_WAIT0();
        __syncthreads();
    }

    // ---- reduce: quad (4 lanes sharing a row) -> smem -> across 4 wn warps
    float* redv = (float*)(dsm + SM_RV);
    int*   redi = (int*)(dsm + SM_RI);
    #pragma unroll
    for (int mi = 0; mi < 4; mi++) {
        #pragma unroll
        for (int h = 0; h < 2; h++) {
            int slot = mi * 2 + h;
            float v = best[slot];
            int   bi = bidx[slot];
            #pragma unroll
            for (int o = 2; o > 0; o >>= 1) {
                float ov = __shfl_down_sync(0xffffffffu, v, o, 4);
                int   oi = __shfl_down_sync(0xffffffffu, bi, o, 4);
                if (ov > v || (ov == v && oi < bi)) { v = ov; bi = oi; }
            }
            if ((lane & 3) == 0) {
                int lrow = wm * 64 + mi * 16 + (lane >> 2) + h * 8;
                redv[lrow * 4 + wn] = v;
                redi[lrow * 4 + wn] = bi;
            }
        }
    }
    __syncthreads();
    if (tid < 128) {
        float v = redv[tid * 4];
        int   bi = redi[tid * 4];
        #pragma unroll
        for (int w = 1; w < 4; w++) {
            float ov = redv[tid * 4 + w];
            int   oi = redi[tid * 4 + w];
            if (ov > v || (ov == v && oi < bi)) { v = ov; bi = oi; }
        }
        g_idx[(size_t)c * AN + row0 + tid] = bi;
    }
}

// ---------------------------------------------------------------------------
// Kernel 3: per-pair distance + partial loss (fp32; PDIST_EPS per-component)
// ---------------------------------------------------------------------------
__global__ void k_dist() {
    int gwarp  = (blockIdx.x * blockDim.x + threadIdx.x) >> 5;
    int lane   = threadIdx.x & 31;
    int nwarps = (gridDim.x * blockDim.x) >> 5;
    float acc = 0.0f;
    for (int item = gwarp; item < CN * AN; item += nwarps) {
        int b = g_idx[item];
        int c = item >> 12;
        const float2* pa = (const float2*)(g_xn + (size_t)item * FN);
        const float2* pb = (const float2*)(g_xn + ((size_t)c * AN + b) * FN);
        float2 va = pa[lane];
        float2 vb = pb[lane];
        float dx = va.x - vb.x + 1e-6f;
        float dy = va.y - vb.y + 1e-6f;
        float ss = dx * dx + dy * dy;
        #pragma unroll
        for (int o = 16; o > 0; o >>= 1) ss += __shfl_xor_sync(0xffffffffu, ss, o);
        if (lane == 0) acc -= logf(sqrtf(ss) + 1e-6f);
    }
    __shared__ float wsum[8];
    if (lane == 0) wsum[threadIdx.x >> 5] = acc;
    __syncthreads();
    if (threadIdx.x == 0) {
        float s = 0.0f;
        #pragma unroll
        for (int i = 0; i < 8; i++) s += wsum[i];
        g_partial[blockIdx.x] = s;
    }
}

__global__ void k_final(float* __restrict__ out) {
    __shared__ float smf[256];
    smf[threadIdx.x] = g_partial[threadIdx.x];
    __syncthreads();
    for (int s = 128; s > 0; s >>= 1) {
        if (threadIdx.x < s) smf[threadIdx.x] += smf[threadIdx.x + s];
        __syncthreads();
    }
    if (threadIdx.x == 0) out[0] = smf[0] / (float)(CN * AN);
}

// ---------------------------------------------------------------------------
extern "C" void kernel_launch(void* const* d_in, const int* in_sizes, int n_in,
                              void* d_out, int out_size) {
    const float* x = (const float*)d_in[0];
    float* out = (float*)d_out;
    (void)in_sizes; (void)n_in; (void)out_size;

    cudaFuncSetAttribute(k_argmax_mma,
                         cudaFuncAttributeMaxDynamicSharedMemorySize, SMEM_BYTES);

    k_normalize<<<(AN * CN) / 8, NTHREADS>>>(x);
    k_argmax_mma<<<dim3(AN / 128, CN), NTHREADS, SMEM_BYTES>>>();
    k_dist<<<256, NTHREADS>>>();
    k_final<<<1, 256>>>(out);
}

// round 5
// speedup vs baseline: 7.5812x; 1.7513x over previous
#include <cuda_runtime.h>
#include <cuda_bf16.h>
#include <math.h>
#include <stdint.h>

#define AN 4096
#define CN 8
#define FN 64
#define NTHREADS 256

// ---------------- device scratch (no allocation allowed) --------------------
__device__ float              g_xn[CN * AN * FN];   // [c][a][f] normalized fp32
__device__ __nv_bfloat16      g_xp[CN * AN * 128];  // [c][a][hi(64)|lo(64)] bf16
__device__ unsigned long long g_best[CN * AN];      // packed (ord(val), 4095-idx)
__device__ float              g_partial[256];

// ---------------- PTX helpers (generic sm_80+ ISA only) ---------------------
static __device__ __forceinline__ uint32_t smem_u32(const void* p) {
    uint32_t a;
    asm("{ .reg .u64 t; cvta.to.shared.u64 t, %1; cvt.u32.u64 %0, t; }"
        : "=r"(a) : "l"(p));
    return a;
}

#define CP16(dst, src) \
    asm volatile("cp.async.cg.shared.global [%0], [%1], 16;" :: "r"(dst), "l"(src))
#define CP_COMMIT() asm volatile("cp.async.commit_group;" ::: "memory")
#define CP_WAIT0()  asm volatile("cp.async.wait_group 0;" ::: "memory")
#define CP_WAIT1()  asm volatile("cp.async.wait_group 1;" ::: "memory")

static __device__ __forceinline__ void ldsm_x4(uint32_t* d, uint32_t addr) {
    asm volatile("ldmatrix.sync.aligned.m8n8.x4.shared.b16 {%0,%1,%2,%3}, [%4];"
                 : "=r"(d[0]), "=r"(d[1]), "=r"(d[2]), "=r"(d[3]) : "r"(addr));
}

static __device__ __forceinline__ void mma_bf16(float* c, const uint32_t* a,
                                                const uint32_t* b) {
    asm volatile(
        "mma.sync.aligned.m16n8k16.row.col.f32.bf16.bf16.f32 "
        "{%0,%1,%2,%3}, {%4,%5,%6,%7}, {%8,%9}, {%0,%1,%2,%3};"
        : "+f"(c[0]), "+f"(c[1]), "+f"(c[2]), "+f"(c[3])
        : "r"(a[0]), "r"(a[1]), "r"(a[2]), "r"(a[3]), "r"(b[0]), "r"(b[1]));
}

// swizzled byte offset of 16B chunk (r, ch) in a 128-row x 256B tile
static __device__ __forceinline__ uint32_t swz(uint32_t r, uint32_t ch) {
    return r * 256u + (((ch & 8u) | ((ch ^ r) & 7u)) << 4);
}

// order-preserving float->u32, packed with (4095 - idx) so that u64-max =
// (max value, then min index) — exactly jnp.argmax tie-break semantics.
static __device__ __forceinline__ unsigned long long pack_key(float v, int idx) {
    uint32_t u = __float_as_uint(v);
    u = (u & 0x80000000u) ? ~u : (u | 0x80000000u);
    return ((unsigned long long)u << 32) | (uint32_t)(4095 - idx);
}

// ---------------------------------------------------------------------------
// Kernel 1: normalize + hi/lo bf16 split + zero g_best
// ---------------------------------------------------------------------------
__global__ void k_normalize(const float* __restrict__ x) {
    int gtid = blockIdx.x * blockDim.x + threadIdx.x;
    if (gtid < CN * AN) g_best[gtid] = 0ull;   // any real key > 0

    int warp = gtid >> 5;
    int lane = threadIdx.x & 31;
    if (warp >= AN * CN) return;
    int a = warp / CN;
    int c = warp % CN;
    const float2* row = (const float2*)(x + ((size_t)a * CN + c) * FN);
    float2 v = row[lane];
    float ss = v.x * v.x + v.y * v.y;
    #pragma unroll
    for (int o = 16; o > 0; o >>= 1) ss += __shfl_xor_sync(0xffffffffu, ss, o);
    float inv = 1.0f / fmaxf(sqrtf(ss), 1e-6f);
    float nx = v.x * inv, ny = v.y * inv;

    float2* dst = (float2*)(g_xn + ((size_t)c * AN + a) * FN);
    dst[lane] = make_float2(nx, ny);

    __nv_bfloat16 hx = __float2bfloat16(nx);
    __nv_bfloat16 hy = __float2bfloat16(ny);
    __nv_bfloat16 lx = __float2bfloat16(nx - __bfloat162float(hx));
    __nv_bfloat16 ly = __float2bfloat16(ny - __bfloat162float(hy));
    __nv_bfloat16* base = g_xp + ((size_t)c * AN + a) * 128;
    __nv_bfloat162 h2; h2.x = hx; h2.y = hy;
    __nv_bfloat162 l2; l2.x = lx; l2.y = ly;
    ((__nv_bfloat162*)base)[lane]        = h2;
    ((__nv_bfloat162*)(base + 64))[lane] = l2;
}

// ---------------------------------------------------------------------------
// Kernel 2: symmetric-triangle GEMM argmax.
// CTA = (strip-pair p, half h, channel c). Strip pair = row-blocks {p, 31-p};
// jobs (i,j>=i) interleaved by h. Row pass accumulates in regs across the
// strip; col pass (transpose candidates) reduced per tile. Global combine
// via atomicMax on packed keys (order-independent => deterministic).
// ---------------------------------------------------------------------------
#define SM_A   0
#define SM_B0  32768
#define SM_B1  65536
#define SM_RV  98304
#define SM_RI  100352
#define SM_CV  102400
#define SM_CI  103424
#define SMEM_BYTES 104448

extern __shared__ __align__(1024) uint8_t dsm[];

__global__ __launch_bounds__(NTHREADS, 2) void k_argmax_sym() {
    uint32_t sb = smem_u32(dsm);
    int tid = threadIdx.x;
    int lane = tid & 31;
    int wid = tid >> 5;
    int wm = wid >> 2;
    int wn = wid & 3;
    int p = blockIdx.x >> 1;
    int h = blockIdx.x & 1;
    int c = blockIdx.y;
    int i1 = p, i2 = 31 - p, n1 = 32 - p;

    const char* xc = (const char*)(g_xp + (size_t)c * AN * 128);

    uint32_t a_rl = (uint32_t)((lane & 7) + ((lane >> 3) & 1) * 8);
    uint32_t a_cs = (uint32_t)(lane >> 4);
    uint32_t b_nl = (uint32_t)((lane & 7) + (lane >> 4) * 8);
    uint32_t b_cs = (uint32_t)((lane >> 3) & 1);

    float best[8];
    int   bidx[8];
    #pragma unroll
    for (int s = 0; s < 8; s++) { best[s] = -2.0f; bidx[s] = 0; }

    auto flush_rows = [&](int fi) {
        float* redv = (float*)(dsm + SM_RV);
        int*   redi = (int*)(dsm + SM_RI);
        #pragma unroll
        for (int mi = 0; mi < 4; mi++) {
            #pragma unroll
            for (int hh = 0; hh < 2; hh++) {
                int slot = mi * 2 + hh;
                float v = best[slot];
                int   bi = bidx[slot];
                #pragma unroll
                for (int o = 2; o > 0; o >>= 1) {
                    float ov = __shfl_down_sync(0xffffffffu, v, o, 4);
                    int   oi = __shfl_down_sync(0xffffffffu, bi, o, 4);
                    if (ov > v || (ov == v && oi < bi)) { v = ov; bi = oi; }
                }
                if ((lane & 3) == 0) {
                    int lrow = wm * 64 + mi * 16 + (lane >> 2) + hh * 8;
                    redv[lrow * 4 + wn] = v;
                    redi[lrow * 4 + wn] = bi;
                }
            }
        }
        __syncthreads();
        if (tid < 128) {
            float v = redv[tid * 4];
            int   bi = redi[tid * 4];
            #pragma unroll
            for (int w = 1; w < 4; w++) {
                float ov = redv[tid * 4 + w];
                int   oi = redi[tid * 4 + w];
                if (ov > v || (ov == v && oi < bi)) { v = ov; bi = oi; }
            }
            atomicMax((unsigned long long*)&g_best[(size_t)c * AN + fi * 128 + tid],
                      pack_key(v, bi));
        }
        __syncthreads();
    };

    // ---- prologue: A(i1) + first B into buf0 ----
    int curi = i1;
    {
        int j0 = p + h;   // first job: jj = h (< n1 always, n1 >= 17)
        #pragma unroll
        for (int it8 = 0; it8 < 8; it8++) {
            int s = tid + it8 * NTHREADS;
            uint32_t r = (uint32_t)(s >> 4), ch = (uint32_t)(s & 15);
            CP16(sb + SM_A  + swz(r, ch), xc + (size_t)(i1 * 128 + r) * 256 + ch * 16);
            CP16(sb + SM_B0 + swz(r, ch), xc + (size_t)(j0 * 128 + r) * 256 + ch * 16);
        }
        CP_COMMIT();
        CP_WAIT0();
    }
    __syncthreads();

    int it = 0;
    for (int jj = h; jj < 33; jj += 2, it++) {
        int i = (jj < n1) ? i1 : i2;
        int j = (jj < n1) ? (p + jj) : (i2 + (jj - n1));
        bool diag = (i == j);
        uint32_t bufc = sb + ((it & 1) ? SM_B1 : SM_B0);

        if (i != curi) {   // strip switch: flush rows, load new A
            flush_rows(curi);
            #pragma unroll
            for (int s = 0; s < 8; s++) { best[s] = -2.0f; bidx[s] = 0; }
            #pragma unroll
            for (int it8 = 0; it8 < 8; it8++) {
                int s = tid + it8 * NTHREADS;
                uint32_t r = (uint32_t)(s >> 4), ch = (uint32_t)(s & 15);
                CP16(sb + SM_A + swz(r, ch),
                     xc + (size_t)(i * 128 + r) * 256 + ch * 16);
            }
            CP_COMMIT();
            curi = i;
        }

        // prefetch next job's B
        int jj2 = jj + 2;
        if (jj2 < 33) {
            int jn = (jj2 < n1) ? (p + jj2) : (i2 + (jj2 - n1));
            uint32_t bufn = sb + ((it & 1) ? SM_B0 : SM_B1);
            #pragma unroll
            for (int it8 = 0; it8 < 8; it8++) {
                int s = tid + it8 * NTHREADS;
                uint32_t r = (uint32_t)(s >> 4), ch = (uint32_t)(s & 15);
                CP16(bufn + swz(r, ch),
                     xc + (size_t)(jn * 128 + r) * 256 + ch * 16);
            }
            CP_COMMIT();
            CP_WAIT1();   // all but the just-issued prefetch complete
        } else {
            CP_WAIT0();
        }
        __syncthreads();

        // ---- 3-term MMA with fragment reuse ----
        float acc[4][4][4];
        #pragma unroll
        for (int mi = 0; mi < 4; mi++)
            #pragma unroll
            for (int ni = 0; ni < 4; ni++)
                #pragma unroll
                for (int q = 0; q < 4; q++) acc[mi][ni][q] = 0.0f;

        #pragma unroll
        for (int ks = 0; ks < 4; ks++) {
            uint32_t kc = (uint32_t)(ks * 2);
            uint32_t af[4][4], bh[2][4], bl[2][4];
            #pragma unroll
            for (int mi = 0; mi < 4; mi++)
                ldsm_x4(af[mi], sb + SM_A + swz((uint32_t)(wm * 64 + mi * 16) + a_rl, kc + a_cs));
            #pragma unroll
            for (int nh = 0; nh < 2; nh++)
                ldsm_x4(bh[nh], bufc + swz((uint32_t)(wn * 32 + nh * 16) + b_nl, kc + b_cs));
            #pragma unroll
            for (int nh = 0; nh < 2; nh++)
                ldsm_x4(bl[nh], bufc + swz((uint32_t)(wn * 32 + nh * 16) + b_nl, 8u + kc + b_cs));
            #pragma unroll
            for (int mi = 0; mi < 4; mi++)
                #pragma unroll
                for (int ni = 0; ni < 4; ni++)
                    mma_bf16(acc[mi][ni], af[mi], &bh[ni >> 1][(ni & 1) * 2]);
            #pragma unroll
            for (int mi = 0; mi < 4; mi++)
                #pragma unroll
                for (int ni = 0; ni < 4; ni++)
                    mma_bf16(acc[mi][ni], af[mi], &bl[ni >> 1][(ni & 1) * 2]);
            #pragma unroll
            for (int mi = 0; mi < 4; mi++)
                ldsm_x4(af[mi], sb + SM_A + swz((uint32_t)(wm * 64 + mi * 16) + a_rl, 8u + kc + a_cs));
            #pragma unroll
            for (int mi = 0; mi < 4; mi++)
                #pragma unroll
                for (int ni = 0; ni < 4; ni++)
                    mma_bf16(acc[mi][ni], af[mi], &bh[ni >> 1][(ni & 1) * 2]);
        }

        // ---- epilogue: row update (regs) + col candidates ----
        float cbv[8];
        int   cbr[8];
        #pragma unroll
        for (int s = 0; s < 8; s++) { cbv[s] = -2.0f; cbr[s] = 0; }

        #pragma unroll
        for (int mi = 0; mi < 4; mi++) {
            #pragma unroll
            for (int hh = 0; hh < 2; hh++) {
                int slot = mi * 2 + hh;
                int lrow = wm * 64 + mi * 16 + (lane >> 2) + hh * 8;
                #pragma unroll
                for (int ni = 0; ni < 4; ni++) {
                    #pragma unroll
                    for (int q = 0; q < 2; q++) {
                        float v = acc[mi][ni][hh * 2 + q];
                        int cc = wn * 32 + ni * 8 + (lane & 3) * 2 + q;
                        if (diag && cc == lrow) v = -2.0f;
                        if (v > best[slot]) { best[slot] = v; bidx[slot] = j * 128 + cc; }
                        int cs = ni * 2 + q;
                        if (v > cbv[cs]) { cbv[cs] = v; cbr[cs] = curi * 128 + lrow; }
                    }
                }
            }
        }

        if (!diag) {   // col pass: transpose candidates for rows-block j
            float* cv = (float*)(dsm + SM_CV);
            int*   ci = (int*)(dsm + SM_CI);
            #pragma unroll
            for (int s = 0; s < 8; s++) {
                float v = cbv[s];
                int   r = cbr[s];
                #pragma unroll
                for (int o = 16; o > 2; o >>= 1) {   // 16, 8, 4
                    float ov  = __shfl_down_sync(0xffffffffu, v, o);
                    int   orr = __shfl_down_sync(0xffffffffu, r, o);
                    if (ov > v || (ov == v && orr < r)) { v = ov; r = orr; }
                }
                if (lane < 4) {
                    int cc = wn * 32 + (s >> 1) * 8 + lane * 2 + (s & 1);
                    cv[wm * 128 + cc] = v;
                    ci[wm * 128 + cc] = r;
                }
            }
            __syncthreads();
            if (tid < 128) {
                float v0 = cv[tid];
                int   r0 = ci[tid];
                float v1 = cv[128 + tid];
                int   r1 = ci[128 + tid];
                if (v1 > v0) { v0 = v1; r0 = r1; }   // wm1 rows > wm0 rows; tie keeps wm0
                atomicMax((unsigned long long*)&g_best[(size_t)c * AN + j * 128 + tid],
                          pack_key(v0, r0));
            }
        }
        __syncthreads();
    }

    flush_rows(curi);
}

// ---------------------------------------------------------------------------
// Kernel 3: distances + partial loss (unpack idx from g_best)
// ---------------------------------------------------------------------------
__global__ void k_dist() {
    int gwarp  = (blockIdx.x * blockDim.x + threadIdx.x) >> 5;
    int lane   = threadIdx.x & 31;
    int nwarps = (gridDim.x * blockDim.x) >> 5;
    float acc = 0.0f;
    for (int item = gwarp; item < CN * AN; item += nwarps) {
        int b = 4095 - (int)(uint32_t)(g_best[item] & 0xFFFFFFFFull);
        int c = item >> 12;
        const float2* pa = (const float2*)(g_xn + (size_t)item * FN);
        const float2* pb = (const float2*)(g_xn + ((size_t)c * AN + b) * FN);
        float2 va = pa[lane];
        float2 vb = pb[lane];
        float dx = va.x - vb.x + 1e-6f;
        float dy = va.y - vb.y + 1e-6f;
        float ss = dx * dx + dy * dy;
        #pragma unroll
        for (int o = 16; o > 0; o >>= 1) ss += __shfl_xor_sync(0xffffffffu, ss, o);
        if (lane == 0) acc -= logf(sqrtf(ss) + 1e-6f);
    }
    __shared__ float wsum[8];
    if (lane == 0) wsum[threadIdx.x >> 5] = acc;
    __syncthreads();
    if (threadIdx.x == 0) {
        float s = 0.0f;
        #pragma unroll
        for (int i = 0; i < 8; i++) s += wsum[i];
        g_partial[blockIdx.x] = s;
    }
}

__global__ void k_final(float* __restrict__ out) {
    __shared__ float smf[256];
    smf[threadIdx.x] = g_partial[threadIdx.x];
    __syncthreads();
    for (int s = 128; s > 0; s >>= 1) {
        if (threadIdx.x < s) smf[threadIdx.x] += smf[threadIdx.x + s];
        __syncthreads();
    }
    if (threadIdx.x == 0) out[0] = smf[0] / (float)(CN * AN);
}

// ---------------------------------------------------------------------------
extern "C" void kernel_launch(void* const* d_in, const int* in_sizes, int n_in,
                              void* d_out, int out_size) {
    const float* x = (const float*)d_in[0];
    float* out = (float*)d_out;
    (void)in_sizes; (void)n_in; (void)out_size;

    cudaFuncSetAttribute(k_argmax_sym,
                         cudaFuncAttributeMaxDynamicSharedMemorySize, SMEM_BYTES);

    k_normalize<<<(AN * CN) / 8, NTHREADS>>>(x);
    k_argmax_sym<<<dim3(32, CN), NTHREADS, SMEM_BYTES>>>();
    k_dist<<<256, NTHREADS>>>();
    k_final<<<1, 256>>>(out);
}